// round 12
// baseline (speedup 1.0000x reference)
#include <cuda_runtime.h>
#include <cuda_bf16.h>
#include <cstdint>

// Problem constants
#define BATCH   16384
#define IN_DIM  784
#define INTER   1024
#define CODE    2048   // STRIPE_DIM(64) * NUM_STRIPES(32)
#define KNEUR   64
#define KSTRIPE 4
#define NSTRIPE 32
#define KPAD1   800    // IN_DIM padded to multiple of 32
#define W4ROWS  896    // IN_DIM padded to multiple of 128 (N tiles for gemm4)

// ---------------------------------------------------------------------------
// Scratch (device globals; no allocation allowed)
// hi/lo tf32 plane pairs; perm8(k) = ((k&3)<<1)|(k>>2) column layout so that
// (k, k+4) mma fragment pairs are adjacent -> LDS.64 fragment loads.
// ---------------------------------------------------------------------------
__device__ float g_xhi[(size_t)BATCH * KPAD1];
__device__ float g_xlo[(size_t)BATCH * KPAD1];
__device__ float g_w1hi[(size_t)INTER * KPAD1];
__device__ float g_w1lo[(size_t)INTER * KPAD1];
__device__ float g_w2hi[(size_t)CODE * INTER];
__device__ float g_w2lo[(size_t)CODE * INTER];
__device__ float g_w4hi[(size_t)W4ROWS * INTER];
__device__ float g_w4lo[(size_t)W4ROWS * INTER];
__device__ float g_hhi[(size_t)BATCH * INTER];
__device__ float g_hlo[(size_t)BATCH * INTER];
__device__ float g_dhi[(size_t)BATCH * INTER];
__device__ float g_dlo[(size_t)BATCH * INTER];
__device__ float g_c[(size_t)BATCH * CODE];
__device__ float g_W3t[(size_t)CODE * INTER];
__device__ float g_vals[(size_t)BATCH * KNEUR];
__device__ int   g_idx[(size_t)BATCH * KNEUR];
__device__ int   g_cnt[BATCH];

__device__ __forceinline__ int perm8(int k)    { return ((k & 3) << 1) | (k >> 2); }
__device__ __forceinline__ int invperm8(int p) { return ((p & 1) << 2) | (p >> 1); }

__device__ __forceinline__ float2 split_tf32(float x) {
    uint32_t u;
    asm("cvt.rna.tf32.f32 %0, %1;" : "=r"(u) : "f"(x));
    float hi = __uint_as_float(u);
    float r  = __fsub_rn(x, hi);
    uint32_t ul;
    asm("cvt.rna.tf32.f32 %0, %1;" : "=r"(ul) : "f"(r));
    return make_float2(hi, __uint_as_float(ul));
}

// ---------------------------------------------------------------------------
// split_plane: src [Rin, Kin] fp32 -> hi/lo planes [Rpad, Kpad], perm8 cols.
// ---------------------------------------------------------------------------
__global__ __launch_bounds__(256)
void split_plane(const float* __restrict__ src, float* __restrict__ hi,
                 float* __restrict__ lo, int Rin, int Kin, int Kpad)
{
    size_t idx = (size_t)blockIdx.x * 256 + threadIdx.x;
    int r  = (int)(idx / Kpad);
    int kc = (int)(idx % Kpad);
    int k  = (kc & ~7) | invperm8(kc & 7);
    float v = 0.f;
    if (r < Rin && k < Kin) v = src[(size_t)r * Kin + k];
    float2 s = split_tf32(v);
    hi[idx] = s.x;
    lo[idx] = s.y;
}

// ---------------------------------------------------------------------------
// Split-TF32 emulated-fp32 tensor GEMM, 2-stage cp.async pipeline.
//   C[M,N] = relu(A[M,K] @ B[N,K]^T + bias[N])
// Block tile 128x128 (256 thr), warp tile 32x64 (8 warps, 4x2).
// Per k-tile (K=32): hi*hi + hi*lo + lo*hi accumulate into one mma register
// accumulator, folded once per tile into (chi, clo) via Fast2Sum.
// MODE 0: plain fp32 store (guard cc<N). MODE 1: split-plane store.
// smem: 2 stages x (A 2x128x40f + B 2x128x40f) = 160 KB.
// ---------------------------------------------------------------------------
#define STAGE_BYTES 81920
#define A_LO_OFF    20480
#define B_OFF       40960
#define B_LO_OFF    20480
#define GEMM_SMEM_BYTES (2 * STAGE_BYTES)   // 163840

__device__ __forceinline__ void cpa16(uint32_t dst, const float* src) {
    asm volatile("cp.async.ca.shared.global [%0], [%1], 16;" :: "r"(dst), "l"(src));
}

__device__ __forceinline__ void mma_tf32(float c[4], const float a[4], const float b[2]) {
    asm volatile(
        "mma.sync.aligned.m16n8k8.row.col.f32.tf32.tf32.f32 "
        "{%0,%1,%2,%3}, {%4,%5,%6,%7}, {%8,%9}, {%0,%1,%2,%3};\n"
        : "+f"(c[0]), "+f"(c[1]), "+f"(c[2]), "+f"(c[3])
        : "r"(__float_as_uint(a[0])), "r"(__float_as_uint(a[1])),
          "r"(__float_as_uint(a[2])), "r"(__float_as_uint(a[3])),
          "r"(__float_as_uint(b[0])), "r"(__float_as_uint(b[1])));
}

template<int MODE>
__global__ __launch_bounds__(256)
void gemm_tc(const float* __restrict__ Ahi, const float* __restrict__ Alo,
             const float* __restrict__ Bhi, const float* __restrict__ Blo,
             const float* __restrict__ bias, float* __restrict__ O1,
             float* __restrict__ O2, int N, int Kpad, int KT)
{
    extern __shared__ char smem[];
    uint32_t smem_u;
    asm("{ .reg .u64 t; cvta.to.shared.u64 t, %1; cvt.u32.u64 %0, t; }"
        : "=r"(smem_u) : "l"(smem));

    const int tid  = threadIdx.x;
    const int wid  = tid >> 5, lane = tid & 31;
    const int row0 = blockIdx.y * 128, col0 = blockIdx.x * 128;
    const int wr = wid >> 1, wc = wid & 1;      // 4 x 2 warps; warp tile 32x64

    float chi[16][4], clo[16][4], acc[16][4];
    #pragma unroll
    for (int f = 0; f < 16; ++f)
        #pragma unroll
        for (int e = 0; e < 4; ++e) { chi[f][e] = 0.f; clo[f][e] = 0.f; acc[f][e] = 0.f; }

    // ---- async stage loader: A and B each 128 rows x 32 k x 2 planes ----
    auto load_stage = [&](int st, int kt) {
        const uint32_t sb = smem_u + st * STAGE_BYTES;
        const int k0 = kt * 32;
        #pragma unroll
        for (int i = 0; i < 8; ++i) {               // A: 2048 16B chunks
            int c = tid + i * 256;
            int plane = c >> 10, row = (c >> 3) & 127, ch = c & 7;
            const float* src = (plane ? Alo : Ahi) + (size_t)(row0 + row) * Kpad + k0 + ch * 4;
            cpa16(sb + plane * A_LO_OFF + row * 160 + ch * 16, src);
        }
        #pragma unroll
        for (int i = 0; i < 8; ++i) {               // B: 2048 16B chunks
            int c = tid + i * 256;
            int plane = c >> 10, row = (c >> 3) & 127, ch = c & 7;
            const float* src = (plane ? Blo : Bhi) + (size_t)(col0 + row) * Kpad + k0 + ch * 4;
            cpa16(sb + B_OFF + plane * B_LO_OFF + row * 160 + ch * 16, src);
        }
        asm volatile("cp.async.commit_group;" ::: "memory");
    };

    load_stage(0, 0);

    for (int kt = 0; kt < KT; ++kt) {
        if (kt + 1 < KT) load_stage((kt + 1) & 1, kt + 1);
        if (kt + 1 < KT) asm volatile("cp.async.wait_group 1;" ::: "memory");
        else             asm volatile("cp.async.wait_group 0;" ::: "memory");
        __syncthreads();

        const char* sc = smem + (kt & 1) * STAGE_BYTES;

        #pragma unroll
        for (int fk = 0; fk < 4; ++fk) {
            const int kb = (fk * 8 + (lane & 3) * 2) * 4;   // byte offset within row
            float ah[2][4], al[2][4];
            #pragma unroll
            for (int rf = 0; rf < 2; ++rf) {
                int row = wr * 32 + rf * 16 + (lane >> 2);
                const char* p = sc + row * 160 + kb;
                float2 h0 = *reinterpret_cast<const float2*>(p);
                float2 h1 = *reinterpret_cast<const float2*>(p + 8 * 160);
                ah[rf][0] = h0.x; ah[rf][1] = h1.x; ah[rf][2] = h0.y; ah[rf][3] = h1.y;
                float2 l0 = *reinterpret_cast<const float2*>(p + A_LO_OFF);
                float2 l1 = *reinterpret_cast<const float2*>(p + A_LO_OFF + 8 * 160);
                al[rf][0] = l0.x; al[rf][1] = l1.x; al[rf][2] = l0.y; al[rf][3] = l1.y;
            }
            #pragma unroll
            for (int nf = 0; nf < 8; ++nf) {
                int n = wc * 64 + nf * 8 + (lane >> 2);
                const char* p = sc + B_OFF + n * 160 + kb;
                float2 h = *reinterpret_cast<const float2*>(p);
                float2 l = *reinterpret_cast<const float2*>(p + B_LO_OFF);
                float bh[2] = { h.x, h.y };
                float bl[2] = { l.x, l.y };
                #pragma unroll
                for (int rf = 0; rf < 2; ++rf) {
                    int f = rf * 8 + nf;
                    mma_tf32(acc[f], ah[rf], bh);
                    mma_tf32(acc[f], ah[rf], bl);
                    mma_tf32(acc[f], al[rf], bh);
                }
            }
        }

        // Fold chunk into (chi, clo) via Fast2Sum; reset acc.
        #pragma unroll
        for (int f = 0; f < 16; ++f)
            #pragma unroll
            for (int e = 0; e < 4; ++e) {
                float a = chi[f][e], p = acc[f][e];
                float s = __fadd_rn(a, p);
                float z = __fsub_rn(s, a);
                clo[f][e] = __fadd_rn(clo[f][e], __fsub_rn(p, z));
                chi[f][e] = s;
                acc[f][e] = 0.f;
            }
        __syncthreads();
    }

    // Epilogue
    #pragma unroll
    for (int rf = 0; rf < 2; ++rf)
        #pragma unroll
        for (int nf = 0; nf < 8; ++nf) {
            int f = rf * 8 + nf;
            int rbase = row0 + wr * 32 + rf * 16 + (lane >> 2);
            int cbase = col0 + wc * 64 + nf * 8 + ((lane & 3) << 1);
            #pragma unroll
            for (int e = 0; e < 4; ++e) {
                int rr = rbase + ((e >> 1) << 3);
                int cc = cbase + (e & 1);
                if (MODE == 0) {
                    if (cc < N) {
                        double v = (double)chi[f][e] + (double)clo[f][e] + (double)bias[cc];
                        O1[(size_t)rr * N + cc] = fmaxf((float)v, 0.f);
                    }
                } else {
                    double v = (double)chi[f][e] + (double)clo[f][e] + (double)bias[cc];
                    float o = fmaxf((float)v, 0.f);
                    float2 s = split_tf32(o);
                    int pc = (cc & ~7) | perm8(cc & 7);
                    O1[(size_t)rr * N + pc] = s.x;
                    O2[(size_t)rr * N + pc] = s.y;
                }
            }
        }
}

// ---------------------------------------------------------------------------
// W3 [1024,2048] -> g_W3t [2048,1024]
// ---------------------------------------------------------------------------
__global__ void transpose_w3(const float* __restrict__ W3)
{
    __shared__ float t[32][33];
    int x = blockIdx.x * 32 + threadIdx.x;
    int y = blockIdx.y * 32 + threadIdx.y;
    t[threadIdx.y][threadIdx.x] = W3[(size_t)y * CODE + x];
    __syncthreads();
    int xo = blockIdx.y * 32 + threadIdx.x;
    int yo = blockIdx.x * 32 + threadIdx.y;
    g_W3t[(size_t)yo * INTER + xo] = t[threadIdx.x][threadIdx.y];
}

// ---------------------------------------------------------------------------
// Per-row top-64 of 2048 (radix select on fp32 bits; all values >= 0),
// stripe sums in fp64, top-4-of-32 stripes, compact (idx, val) emission.
// ---------------------------------------------------------------------------
__global__ __launch_bounds__(256)
void topk_compact()
{
    const int row = blockIdx.x;
    const int tid = threadIdx.x;

    __shared__ unsigned bits[CODE];
    __shared__ unsigned hist[256];
    __shared__ unsigned s_prefix;
    __shared__ int s_k;
    __shared__ double s_sum[NSTRIPE];
    __shared__ int s_mask[NSTRIPE];
    __shared__ int s_cnt;

    const unsigned* crow = reinterpret_cast<const unsigned*>(g_c + (size_t)row * CODE);
    #pragma unroll
    for (int i = 0; i < 2; ++i) {
        int f = tid + i * 256;
        reinterpret_cast<uint4*>(bits)[f] = reinterpret_cast<const uint4*>(crow)[f];
    }
    if (tid == 0) { s_prefix = 0u; s_k = KNEUR; s_cnt = 0; }
    __syncthreads();

    for (int p = 3; p >= 0; --p) {
        hist[tid] = 0u;
        __syncthreads();
        unsigned prefix = s_prefix;
        unsigned himask = (p == 3) ? 0u : (0xFFFFFFFFu << ((p + 1) * 8));
        #pragma unroll
        for (int i = 0; i < 8; ++i) {
            unsigned b = bits[tid * 8 + i];
            if ((b & himask) == prefix)
                atomicAdd(&hist[(b >> (p * 8)) & 0xFFu], 1u);
        }
        __syncthreads();
        #pragma unroll
        for (int off = 1; off < 256; off <<= 1) {
            unsigned v = (tid + off < 256) ? hist[tid + off] : 0u;
            __syncthreads();
            hist[tid] += v;
            __syncthreads();
        }
        unsigned kk = (unsigned)s_k;
        unsigned ge = hist[tid];
        unsigned gt = (tid < 255) ? hist[tid + 1] : 0u;
        __syncthreads();
        if (ge >= kk && gt < kk) {
            s_prefix = prefix | ((unsigned)tid << (p * 8));
            s_k = (int)(kk - gt);
        }
        __syncthreads();
    }
    const unsigned T = s_prefix;

    float mv[8];
    double partial = 0.0;
    #pragma unroll
    for (int i = 0; i < 8; ++i) {
        unsigned b = bits[tid * 8 + i];
        float v = __uint_as_float(b);
        float m = (b >= T) ? v : 0.f;
        mv[i] = m;
        partial += (double)m;
    }
    partial += __shfl_down_sync(0xffffffffu, partial, 4);
    partial += __shfl_down_sync(0xffffffffu, partial, 2);
    partial += __shfl_down_sync(0xffffffffu, partial, 1);
    if ((tid & 7) == 0) s_sum[tid >> 3] = partial;
    __syncthreads();

    if (tid < NSTRIPE) {
        double my = s_sum[tid];
        int c = 0;
        #pragma unroll
        for (int j = 0; j < NSTRIPE; ++j) c += (s_sum[j] > my);
        s_mask[tid] = (c < KSTRIPE);
    }
    __syncthreads();

    const int keep = s_mask[tid >> 3];
    #pragma unroll
    for (int i = 0; i < 8; ++i) {
        float m = mv[i];
        if (keep && m > 0.f) {
            int pos = atomicAdd(&s_cnt, 1);
            if (pos < KNEUR) {
                g_vals[(size_t)row * KNEUR + pos] = m;
                g_idx[(size_t)row * KNEUR + pos]  = tid * 8 + i;
            }
        }
    }
    __syncthreads();
    if (tid == 0) g_cnt[row] = min(s_cnt, KNEUR);
}

// ---------------------------------------------------------------------------
// Sparse decode: d[row,:] = relu(b3 + sum_i val_i * W3t[idx_i, :]),
// written directly as split hi/lo planes (perm8 layout) for gemm4.
// ---------------------------------------------------------------------------
__global__ __launch_bounds__(256)
void sparse_decode(const float* __restrict__ b3)
{
    const int row = blockIdx.x;
    const int tid = threadIdx.x;
    __shared__ float sv[KNEUR];
    __shared__ int   si[KNEUR];

    const int cnt = g_cnt[row];
    if (tid < cnt) {
        sv[tid] = g_vals[(size_t)row * KNEUR + tid];
        si[tid] = g_idx[(size_t)row * KNEUR + tid];
    }
    __syncthreads();

    float4 acc = make_float4(0.f, 0.f, 0.f, 0.f);
    for (int i = 0; i < cnt; ++i) {
        float v = sv[i];
        float4 w = *reinterpret_cast<const float4*>(&g_W3t[(size_t)si[i] * INTER + tid * 4]);
        acc.x = fmaf(v, w.x, acc.x);
        acc.y = fmaf(v, w.y, acc.y);
        acc.z = fmaf(v, w.z, acc.z);
        acc.w = fmaf(v, w.w, acc.w);
    }
    float4 bb = *reinterpret_cast<const float4*>(b3 + tid * 4);
    float o[4];
    o[0] = fmaxf(acc.x + bb.x, 0.f);
    o[1] = fmaxf(acc.y + bb.y, 0.f);
    o[2] = fmaxf(acc.z + bb.z, 0.f);
    o[3] = fmaxf(acc.w + bb.w, 0.f);
    #pragma unroll
    for (int j = 0; j < 4; ++j) {
        int cc = tid * 4 + j;
        int pc = (cc & ~7) | perm8(cc & 7);
        float2 s = split_tf32(o[j]);
        g_dhi[(size_t)row * INTER + pc] = s.x;
        g_dlo[(size_t)row * INTER + pc] = s.y;
    }
}

// ---------------------------------------------------------------------------
// Launch
// ---------------------------------------------------------------------------
extern "C" void kernel_launch(void* const* d_in, const int* in_sizes, int n_in,
                              void* d_out, int out_size)
{
    const float* x  = (const float*)d_in[0];
    const float* W1 = (const float*)d_in[1];
    const float* b1 = (const float*)d_in[2];
    const float* W2 = (const float*)d_in[3];
    const float* b2 = (const float*)d_in[4];
    const float* W3 = (const float*)d_in[5];
    const float* b3 = (const float*)d_in[6];
    const float* W4 = (const float*)d_in[7];
    const float* b4 = (const float*)d_in[8];
    float* out = (float*)d_out;

    float *xhi, *xlo, *w1hi, *w1lo, *w2hi, *w2lo, *w4hi, *w4lo;
    float *hhi, *hlo, *dhi, *dlo, *c;
    cudaGetSymbolAddress((void**)&xhi,  g_xhi);  cudaGetSymbolAddress((void**)&xlo,  g_xlo);
    cudaGetSymbolAddress((void**)&w1hi, g_w1hi); cudaGetSymbolAddress((void**)&w1lo, g_w1lo);
    cudaGetSymbolAddress((void**)&w2hi, g_w2hi); cudaGetSymbolAddress((void**)&w2lo, g_w2lo);
    cudaGetSymbolAddress((void**)&w4hi, g_w4hi); cudaGetSymbolAddress((void**)&w4lo, g_w4lo);
    cudaGetSymbolAddress((void**)&hhi,  g_hhi);  cudaGetSymbolAddress((void**)&hlo,  g_hlo);
    cudaGetSymbolAddress((void**)&dhi,  g_dhi);  cudaGetSymbolAddress((void**)&dlo,  g_dlo);
    cudaGetSymbolAddress((void**)&c,    g_c);

    static bool attr_set = false;
    if (!attr_set) {
        cudaFuncSetAttribute(gemm_tc<0>, cudaFuncAttributeMaxDynamicSharedMemorySize, GEMM_SMEM_BYTES);
        cudaFuncSetAttribute(gemm_tc<1>, cudaFuncAttributeMaxDynamicSharedMemorySize, GEMM_SMEM_BYTES);
        attr_set = true;
    }

    // Pre-split inputs into hi/lo tf32 planes (perm8 column layout, padded)
    split_plane<<<(unsigned)(((size_t)BATCH * KPAD1) / 256), 256>>>(x,  xhi,  xlo,  BATCH, IN_DIM, KPAD1);
    split_plane<<<(unsigned)(((size_t)INTER * KPAD1) / 256), 256>>>(W1, w1hi, w1lo, INTER, IN_DIM, KPAD1);
    split_plane<<<(unsigned)(((size_t)CODE * INTER) / 256), 256>>>(W2, w2hi, w2lo, CODE, INTER, INTER);
    split_plane<<<(unsigned)(((size_t)W4ROWS * INTER) / 256), 256>>>(W4, w4hi, w4lo, IN_DIM, INTER, INTER);
    transpose_w3<<<dim3(CODE / 32, INTER / 32), dim3(32, 32)>>>(W3);

    // GEMM1: h = relu(x @ W1^T + b1) -> split h planes  (K=800pad, 25 ktiles)
    gemm_tc<1><<<dim3(INTER / 128, BATCH / 128), 256, GEMM_SMEM_BYTES>>>(
        xhi, xlo, w1hi, w1lo, b1, hhi, hlo, INTER, KPAD1, KPAD1 / 32);

    // GEMM2: c = relu(h @ W2^T + b2) -> plain fp32      (K=1024, 32 ktiles)
    gemm_tc<0><<<dim3(CODE / 128, BATCH / 128), 256, GEMM_SMEM_BYTES>>>(
        hhi, hlo, w2hi, w2lo, b2, c, nullptr, CODE, INTER, INTER / 32);

    // Top-k masks + compaction
    topk_compact<<<BATCH, 256>>>();

    // Sparse GEMM3 -> split d planes
    sparse_decode<<<BATCH, 256>>>(b3);

    // GEMM4: out = relu(d @ W4^T + b4)  (N=784 store guard, 7 N-tiles)
    gemm_tc<0><<<dim3(W4ROWS / 128, BATCH / 128), 256, GEMM_SMEM_BYTES>>>(
        dhi, dlo, w4hi, w4lo, b4, out, nullptr, IN_DIM, INTER, INTER / 32);
}